// round 15
// baseline (speedup 1.0000x reference)
#include <cuda_runtime.h>
#include <cuda_bf16.h>
#include <cstdint>

// x:       (L=2048, B=16) int32   -> x[l*16 + b]
// embed_w: (V=50257, D=1024) fp32 -> w[t*1024 + d]
// out:     (B=16, D=1024, L=2048) fp32 -> out[b*D*L + d*L + l]
// rows with token >= 20 are zero; output scaled by sqrt(8).

#define L_DIM   2048
#define B_DIM   16
#define D_DIM   1024
#define MAXTOK  20
#define SCALE   2.8284271247461903f  // sqrt(8)

#define NBLK    4096
#define TPB     256
#define ZITER   4
#define STRIDE  (1u << 20)   // NBLK*TPB; total v8 elems = 4*2^20 = 4194304

// 256 l8-groups (l8 = l/8). Bit g of word (8 words): any token < MAXTOK
// for l in [8g, 8g+8), any b  (= 128 tokens = 32 int4).
__device__ unsigned g_mask8[8];

// ---------------------------------------------------------------------------
// Kernel 1: build 256-bit l8 mask. 8 blocks x 1 warp.
// Iteration j: 32 lanes read group (32*wi+j)'s 32 int4 (512B coalesced),
// ballot -> one bit.
// ---------------------------------------------------------------------------
__global__ void __launch_bounds__(32) mask_kernel(const int* __restrict__ x)
{
    const int wi   = blockIdx.x;          // word 0..7, groups [32wi,32wi+32)
    const int lane = threadIdx.x;
    const int4* src = (const int4*)x + wi * 1024;

    unsigned word = 0;
    #pragma unroll
    for (int j = 0; j < 32; j++) {
        int4 v = __ldg(src + j * 32 + lane);
        int m = min(min(v.x, v.y), min(v.z, v.w));
        unsigned bal = __ballot_sync(0xFFFFFFFFu, m < MAXTOK);
        word |= (bal ? 1u : 0u) << j;
    }
    if (lane == 0) g_mask8[wi] = word;
}

// ---------------------------------------------------------------------------
// Kernel 2: 256-bit-store zero fill + warp-cooperative fixup.
// idx (v8 units): l8 = idx&255, d = (idx>>8)&1023 (warp-uniform),
// b = idx>>18; STRIDE bumps b by 4 per iteration (b0, b0+4, b0+8, b0+12).
// Warp lanes = 32 consecutive l8 = one aligned mask word.
// ---------------------------------------------------------------------------
__global__ void __launch_bounds__(TPB) fill_kernel(
    const int* __restrict__ x,
    const float* __restrict__ w,
    float* __restrict__ out)
{
    const unsigned idx0 = blockIdx.x * TPB + threadIdx.x;

    // --- zero sweep with 256-bit stores ---
    unsigned idx = idx0;
    #pragma unroll
    for (int k = 0; k < ZITER; k++) {
        char* p = (char*)out + (size_t)idx * 32;
        asm volatile(
            "st.global.v8.b32 [%0], {%1,%1,%1,%1,%1,%1,%1,%1};"
            :: "l"(p), "r"(0u) : "memory");
        idx += STRIDE;
    }

    // --- warp-uniform predicate (one aligned 32-bit window per warp) ---
    const int w8 = (idx0 >> 5) & 7;          // warp's mask word index
    unsigned word = g_mask8[w8];
    if (word == 0) return;

    __syncwarp();                            // order fixup after zero stores

    // --- fixup: per set bit, 32 lanes cover 8l x 4b (exactly this warp's
    //     cells for that l8-group across its 4 b-phases) ---
    const int d     = (idx0 >> 8) & 1023;    // warp-uniform
    const int b0    = idx0 >> 18;            // warp-uniform phase (0..3)
    const int lane  = threadIdx.x & 31;
    const int l_off = lane >> 2;             // 0..7
    const int b     = b0 + 4 * (lane & 3);   // this thread's b set
    const int gbase = w8 << 5;

    while (word) {                           // uniform loop, ~1-2 iterations
        int g = __ffs(word) - 1;
        word &= word - 1;
        int l = ((gbase + g) << 3) + l_off;
        int t = __ldg(x + l * B_DIM + b);    // 512B L2-hot region
        if (t < MAXTOK) {
            out[(size_t)b * (D_DIM * L_DIM) + (size_t)d * L_DIM + l] =
                __ldg(w + (size_t)t * D_DIM + d) * SCALE;
        }
    }
}

// ---------------------------------------------------------------------------
extern "C" void kernel_launch(void* const* d_in, const int* in_sizes, int n_in,
                              void* d_out, int out_size)
{
    const int*   x = (const int*)d_in[0];
    const float* w = (const float*)d_in[1];

    mask_kernel<<<8, 32>>>(x);
    fill_kernel<<<NBLK, TPB>>>(x, w, (float*)d_out);
}

// round 16
// speedup vs baseline: 1.0988x; 1.0988x over previous
#include <cuda_runtime.h>
#include <cuda_bf16.h>

// x:       (L=2048, B=16) int32   -> x[l*16 + b]
// embed_w: (V=50257, D=1024) fp32 -> w[t*1024 + d]
// out:     (B=16, D=1024, L=2048) fp32 -> out[b*D*L + d*L + l]
// rows with token >= 20 are zero; output scaled by sqrt(8).

#define L_DIM   2048
#define B_DIM   16
#define D_DIM   1024
#define MAXTOK  20
#define SCALE   2.8284271247461903f  // sqrt(8)

#define ZBLOCKS 4096
#define ZTPB    256
#define ZITER   8            // 4096*256*8 = 8388608 float4
#define STRIDE  (1u << 20)   // ZBLOCKS*ZTPB

// Single kernel, no device globals, no cross-block dependencies.
//
// Warp permutation: W = (bid>>4)*128 + wid*16 + (bid&15)  (bijective).
//   -> all 8 warps of a block share l4-window (bid & 15)
//   -> at sweep iteration k the grid still writes the contiguous slab
//      [k*16MB,(k+1)*16MB); each warp store is 512B contiguous (proven
//      LTS-ceiling pattern, ~7 TB/s).
// Mask words are built and published BEFORE the sweep so blocks retire
// straight off their final store (no post-drain syncthreads tail).
__global__ void __launch_bounds__(ZTPB) fused_kernel(
    const int* __restrict__ x,
    const float* __restrict__ w,
    float4* __restrict__ out)
{
    __shared__ unsigned s_parts[8];

    const int tid  = threadIdx.x;
    const int wid  = tid >> 5;
    const int lane = tid & 31;
    const int bid  = blockIdx.x;
    const int wi   = bid & 15;              // this block's l4 window (0..15)

    const unsigned W    = ((unsigned)(bid >> 4) << 7) | ((unsigned)wid << 4) | (unsigned)wi;
    const unsigned idx0 = (W << 5) | (unsigned)lane;

    // ---- token loads: 2 coalesced int4/thread (8KB/block, L2-hot:
    //      256 blocks share each window slice) ----
    const int4* src = (const int4*)x + wi * 512;     // 2048 tokens = 512 int4
    int4 v1 = __ldg(src + tid);
    int4 v2 = __ldg(src + tid + 256);

    // ---- build + publish window detail word BEFORE the sweep ----
    // int4 j covers l4-group j>>4; warp reads j in [32wid,32wid+32) and
    // [256+32wid,...): groups {2wid,2wid+1} and {16+2wid,17+2wid}.
    int m1 = min(min(v1.x, v1.y), min(v1.z, v1.w));
    int m2 = min(min(v2.x, v2.y), min(v2.z, v2.w));
    unsigned bal1 = __ballot_sync(0xFFFFFFFFu, m1 < MAXTOK);
    unsigned bal2 = __ballot_sync(0xFFFFFFFFu, m2 < MAXTOK);
    unsigned part = 0;
    part |= ((bal1 & 0xFFFFu) ? 1u : 0u) << (2 * wid);
    part |= ((bal1 >> 16)     ? 1u : 0u) << (2 * wid + 1);
    part |= ((bal2 & 0xFFFFu) ? 1u : 0u) << (16 + 2 * wid);
    part |= ((bal2 >> 16)     ? 1u : 0u) << (17 + 2 * wid);
    if (lane == 0) s_parts[wid] = part;
    __syncthreads();                        // cheap here: nothing in flight yet

    // ---- unconditional zero sweep (proven LTS-ceiling pattern) ----
    const float4 z = make_float4(0.f, 0.f, 0.f, 0.f);
    unsigned idx = idx0;
    #pragma unroll
    for (int k = 0; k < ZITER; k++) {
        __stcs(out + idx, z);
        idx += STRIDE;
    }

    // ---- predicate: bare smem read, no further sync needed ----
    unsigned word = s_parts[0] | s_parts[1] | s_parts[2] | s_parts[3]
                  | s_parts[4] | s_parts[5] | s_parts[6] | s_parts[7];
    if (word == 0) return;                  // block-uniform exit (~45%)

    __syncwarp();                           // order fixup after zero stores

    // ---- cooperative fixup (validated): 32 lanes cover 4l x 8b per bit ----
    const int d     = (idx0 >> 9) & 1023;   // warp-uniform
    const int b0    = idx0 >> 19;           // warp-uniform b-parity (0/1)
    const int l4w   = wi << 5;              // window's global l4 base
    const int l_off = lane >> 3;            // 0..3
    const int b     = b0 + 2 * (lane & 7);  // parity-matched b
    float* outf = (float*)out;

    while (word) {                          // uniform loop, ~1 iteration
        int g = __ffs(word) - 1;
        word &= word - 1;
        int l = ((l4w + g) << 2) + l_off;
        int t = __ldg(x + l * B_DIM + b);   // 32 lanes: 256B L2-hot region
        if (t < MAXTOK) {
            outf[(size_t)b * (D_DIM * L_DIM) + (size_t)d * L_DIM + l] =
                __ldg(w + (size_t)t * D_DIM + d) * SCALE;
        }
    }
}

extern "C" void kernel_launch(void* const* d_in, const int* in_sizes, int n_in,
                              void* d_out, int out_size)
{
    const int*   x = (const int*)d_in[0];
    const float* w = (const float*)d_in[1];
    fused_kernel<<<ZBLOCKS, ZTPB>>>(x, w, (float4*)d_out);
}

// round 17
// speedup vs baseline: 1.1131x; 1.0130x over previous
#include <cuda_runtime.h>
#include <cuda_bf16.h>

// x:       (L=2048, B=16) int32   -> x[l*16 + b]
// embed_w: (V=50257, D=1024) fp32 -> w[t*1024 + d]
// out:     (B=16, D=1024, L=2048) fp32 -> out[b*D*L + d*L + l]
// rows with token >= 20 are zero; output scaled by sqrt(8).

#define L_DIM   2048
#define B_DIM   16
#define D_DIM   1024
#define MAXTOK  20
#define SCALE   2.8284271247461903f  // sqrt(8)

#define ZBLOCKS 4096
#define ZTPB    256
#define ZITER   8            // 4096*256*8 = 8388608 float4
#define STRIDE  (1u << 20)   // ZBLOCKS*ZTPB

// Single kernel, no device globals, no cross-block dependencies.
// Warp permutation: W = (bid>>4)*128 + wid*16 + (bid&15)  (bijective):
//   all 8 warps of a block share l4-window (bid & 15); sweep iteration k
//   still writes the contiguous slab [k*16MB,(k+1)*16MB) with 512B
//   contiguous warp stores (proven LTS-ceiling pattern).
// NEW: warp 0 is the sole mask producer (pipelined 8KB window read ->
// 32-bit detail word); warps 1-7 start storing at cycle 0. The single
// __syncthreads() after the sweep publishes the word AND orders all zero
// stores before fixup.
__global__ void __launch_bounds__(ZTPB) fused_kernel(
    const int* __restrict__ x,
    const float* __restrict__ w,
    float4* __restrict__ out)
{
    __shared__ unsigned s_word;

    const int tid  = threadIdx.x;
    const int wid  = tid >> 5;
    const int lane = tid & 31;
    const int bid  = blockIdx.x;
    const int wi   = bid & 15;              // this block's l4 window (0..15)

    const unsigned W    = ((unsigned)(bid >> 4) << 7) | ((unsigned)wid << 4) | (unsigned)wi;
    const unsigned idx0 = (W << 5) | (unsigned)lane;

    // ---- producer: warp 0 builds the window's 32-bit detail word ----
    // int4 j (of 512) covers l4-group j>>4; iteration k reads j=k*32+lane
    // -> groups {2k, 2k+1} via ballot halves (identical to validated R6
    // mask_kernel body). 4-deep load pipeline hides L2 latency.
    if (wid == 0) {
        const int4* src = (const int4*)x + wi * 512;
        unsigned word = 0;
        #pragma unroll
        for (int k0 = 0; k0 < 16; k0 += 4) {
            int4 a = __ldg(src + (k0 + 0) * 32 + lane);
            int4 b = __ldg(src + (k0 + 1) * 32 + lane);
            int4 c = __ldg(src + (k0 + 2) * 32 + lane);
            int4 e = __ldg(src + (k0 + 3) * 32 + lane);
            int ma = min(min(a.x, a.y), min(a.z, a.w));
            int mb = min(min(b.x, b.y), min(b.z, b.w));
            int mc = min(min(c.x, c.y), min(c.z, c.w));
            int me = min(min(e.x, e.y), min(e.z, e.w));
            unsigned ba = __ballot_sync(0xFFFFFFFFu, ma < MAXTOK);
            unsigned bb = __ballot_sync(0xFFFFFFFFu, mb < MAXTOK);
            unsigned bc = __ballot_sync(0xFFFFFFFFu, mc < MAXTOK);
            unsigned be = __ballot_sync(0xFFFFFFFFu, me < MAXTOK);
            word |= ((ba & 0xFFFFu) ? 1u : 0u) << (2 * k0 + 0);
            word |= ((ba >> 16)     ? 1u : 0u) << (2 * k0 + 1);
            word |= ((bb & 0xFFFFu) ? 1u : 0u) << (2 * k0 + 2);
            word |= ((bb >> 16)     ? 1u : 0u) << (2 * k0 + 3);
            word |= ((bc & 0xFFFFu) ? 1u : 0u) << (2 * k0 + 4);
            word |= ((bc >> 16)     ? 1u : 0u) << (2 * k0 + 5);
            word |= ((be & 0xFFFFu) ? 1u : 0u) << (2 * k0 + 6);
            word |= ((be >> 16)     ? 1u : 0u) << (2 * k0 + 7);
        }
        if (lane == 0) s_word = word;
    }

    // ---- unconditional zero sweep: warps 1-7 start here immediately ----
    const float4 z = make_float4(0.f, 0.f, 0.f, 0.f);
    unsigned idx = idx0;
    #pragma unroll
    for (int k = 0; k < ZITER; k++) {
        __stcs(out + idx, z);
        idx += STRIDE;
    }

    __syncthreads();   // publish s_word + order all zero stores before fixup

    unsigned word = s_word;
    if (word == 0) return;                  // block-uniform exit (~45%)

    // ---- cooperative fixup (validated): 32 lanes cover 4l x 8b per bit ----
    const int d     = (idx0 >> 9) & 1023;   // warp-uniform
    const int b0    = idx0 >> 19;           // warp-uniform b-parity (0/1)
    const int l4w   = wi << 5;              // window's global l4 base
    const int l_off = lane >> 3;            // 0..3
    const int b     = b0 + 2 * (lane & 7);  // parity-matched b
    float* outf = (float*)out;

    while (word) {                          // uniform loop, ~1 iteration
        int g = __ffs(word) - 1;
        word &= word - 1;
        int l = ((l4w + g) << 2) + l_off;
        int t = __ldg(x + l * B_DIM + b);   // 32 lanes: 256B L2-hot region
        if (t < MAXTOK) {
            outf[(size_t)b * (D_DIM * L_DIM) + (size_t)d * L_DIM + l] =
                __ldg(w + (size_t)t * D_DIM + d) * SCALE;
        }
    }
}

extern "C" void kernel_launch(void* const* d_in, const int* in_sizes, int n_in,
                              void* d_out, int out_size)
{
    const int*   x = (const int*)d_in[0];
    const float* w = (const float*)d_in[1];
    fused_kernel<<<ZBLOCKS, ZTPB>>>(x, w, (float4*)d_out);
}